// round 14
// baseline (speedup 1.0000x reference)
#include <cuda_runtime.h>
#include <cuda_fp16.h>
#include <math.h>
#include <stdint.h>

// Problem constants
#define N1 400000
#define N2 400000
#define N3 800000
#define N4 1200000
#define U  128
#define NTHR 256     // 8 warps, 4m x 2n, warp tile 32x64; 3 CTAs/SM (reg-capped)
#define PW  68       // tile pitch in half2 words (64 data + 4 pad)
#define TILE_WORDS 8704   // 128 rows x 68 words

// ---------------------------------------------------------------------------
// Scratch buffers
// ---------------------------------------------------------------------------
__device__ uint32_t g_H2h[(size_t)N2 * 64];   // fp16 half2 rows
__device__ uint32_t g_H3h[(size_t)N3 * 64];
__device__ float    g_HD3[(size_t)N3 * U];
__device__ float    g_HD2[(size_t)N2 * U];
__device__ float    g_HD1[(size_t)N1 * U];
// 21 weight chunk images (n-major: word[n*68+k2] = half2(k=2k2,2k2+1) at col n)
__device__ uint32_t g_WT[21 * TILE_WORDS];

#define CH_UP2 0
#define CH_UP3 3
#define CH_UP4 6
#define CH_DN3 9
#define CH_DN2 11
#define CH_DN1 13
#define CH_W2(i) (15 + (i))

// ---------------------------------------------------------------------------
// helpers
// ---------------------------------------------------------------------------
__device__ __forceinline__ float fast_tanh(float x) {
    float e = __expf(2.0f * x);
    return 1.0f - __fdividef(2.0f, e + 1.0f);
}
__device__ __forceinline__ uint32_t h2bits(__half2 h) { return *(uint32_t*)&h; }
__device__ __forceinline__ uint32_t pack2(float x, float y) {
    return h2bits(__floats2half2_rn(x, y));
}
__device__ __forceinline__ void cp_async16(void* dst_smem, const void* src) {
    uint32_t d = (uint32_t)__cvta_generic_to_shared(dst_smem);
    asm volatile("cp.async.cg.shared.global [%0], [%1], 16;" :: "r"(d), "l"(src));
}
#define CP_COMMIT() asm volatile("cp.async.commit_group;" ::: "memory")
#define CP_WAIT_0() asm volatile("cp.async.wait_group 0;" ::: "memory")

__device__ __forceinline__ void red_add_v2(float* p, float x, float y) {
    asm volatile("red.global.add.v2.f32 [%0], {%1,%2};"
                 :: "l"(p), "f"(x), "f"(y) : "memory");
}
__device__ __forceinline__ void mma_fp16(float c[4],
                                         uint32_t a0, uint32_t a1, uint32_t a2, uint32_t a3,
                                         uint32_t b0, uint32_t b1) {
    asm volatile(
        "mma.sync.aligned.m16n8k16.row.col.f32.f16.f16.f32 "
        "{%0,%1,%2,%3}, {%4,%5,%6,%7}, {%8,%9}, {%0,%1,%2,%3};"
        : "+f"(c[0]), "+f"(c[1]), "+f"(c[2]), "+f"(c[3])
        : "r"(a0), "r"(a1), "r"(a2), "r"(a3), "r"(b0), "r"(b1));
}

// ---------------------------------------------------------------------------
// Weight prep (one launch): 21 chunks -> n-major fp16 tile images.
// ---------------------------------------------------------------------------
struct PrepPtrs { const float* p[21]; };

__global__ void prep_all(PrepPtrs pp, uint32_t* __restrict__ dst)
{
    int e = blockIdx.x * 256 + threadIdx.x;
    if (e >= 21 * TILE_WORDS) return;
    int chunk = e / TILE_WORDS, w = e - chunk * TILE_WORDS;
    int n = w / PW, k2 = w - n * PW;
    uint32_t v = 0;
    if (k2 < 64) {
        const float* W = pp.p[chunk];
        v = pack2(W[(size_t)(2 * k2) * 128 + n], W[(size_t)(2 * k2 + 1) * 128 + n]);
    }
    dst[e] = v;
}

__global__ void zero_all(float4* __restrict__ hd3, float4* __restrict__ hd2,
                         float4* __restrict__ hd1)
{
    const long Z3 = (long)N3 * 32, Z2 = (long)N2 * 32, Z1 = (long)N1 * 32;
    long i = (long)blockIdx.x * 256 + threadIdx.x;
    if (i >= Z3 + Z2 + Z1) return;
    float4 z = make_float4(0.f, 0.f, 0.f, 0.f);
    if (i < Z3)           hd3[i] = z;
    else if (i < Z3 + Z2) hd2[i - Z3] = z;
    else                  hd1[i - Z3 - Z2] = z;
}

// ---------------------------------------------------------------------------
// fp16 fused gather + MLP (+ fused scatter), mma m16n8k16, 3 CTAs/SM:
//   y[r] = tanh( concat(segments(r)) @ W1 + b1 ) @ W2 + b2
// CTA tile 128x128, 256 threads, 8 warps (4m x 2n), warp tile 32x64.
// A and B single-buffered (69.6KB smem); reg-capped to 84 (launch_bounds 3)
// so 3 CTAs/SM co-reside — cross-CTA overlap hides fill and sync latency.
// Inner loop restructured (B frags per-nh, consumed immediately) to keep the
// live set ~80 regs: acc 64 + a 8 + b 4 + addressing.
// ---------------------------------------------------------------------------
template <int NSEG, bool SCATTER, bool SELF16, bool GAT16, bool OUT16>
__global__ __launch_bounds__(NTHR, 3)
void mlp3(const void* __restrict__ selfp,
          const void* __restrict__ gatp,
          const int*  __restrict__ idxg,
          const uint32_t* __restrict__ WB1,   // NSEG chunk images
          const float* __restrict__ b1,
          const uint32_t* __restrict__ WB2,   // 1 chunk image
          const float* __restrict__ b2,
          void* __restrict__ outp,
          const int* __restrict__ idxs)
{
    extern __shared__ uint32_t smu[];
    uint32_t* smA = smu;                // A tile (then H tile)
    uint32_t* smB = smu + TILE_WORDS;   // W tile

    const int t    = threadIdx.x;
    const int lane = t & 31;
    const int cw   = t >> 5;            // warp 0..7
    const int g    = lane >> 2;
    const int tg   = lane & 3;
    const int wm   = (cw & 3) * 32;     // 4 m-warps
    const int wn   = (cw >> 2) * 64;    // 2 n-warps
    const long r0  = (long)blockIdx.x * 128;
    const int arow = t >> 1;            // A-fill: 2 threads per row
    const int ah   = t & 1;             // row half

    const uint32_t smemU = (uint32_t)__cvta_generic_to_shared(smu);
    const uint32_t Aaddr = smemU;
    const uint32_t Baddr = smemU + TILE_WORDS * 4;

    // ldmatrix lane offsets (bytes) — layout verified rounds 10-13
    const uint32_t aLane = ((wm + (lane & 15)) * PW + (lane >> 4) * 4) * 4;
    const uint32_t bLane = ((wn + (lane & 7) + ((lane >> 4) << 3)) * PW
                            + ((lane >> 3) & 1) * 4) * 4;

    // gather row indices
    long rows[3];
    rows[0] = r0 + arow;
    if (NSEG == 3) {
        int2 gi = __ldg((const int2*)idxg + (r0 + arow));
        rows[1] = gi.x; rows[2] = gi.y;
    } else {
        rows[1] = r0 + arow;
    }

    float accf[2][8][4];
#pragma unroll
    for (int mt = 0; mt < 2; mt++)
#pragma unroll
        for (int nt = 0; nt < 8; nt++)
#pragma unroll
            for (int c = 0; c < 4; c++) accf[mt][nt][c] = 0.f;

    // ---- fill helpers ----
    auto fillA16 = [&](int seg) {   // fp16 source: pure cp.async
        const uint4* src = (const uint4*)(seg == 0 ? selfp : gatp)
                           + rows[seg] * 16 + ah * 8;
        uint32_t* d = smA + arow * PW + ah * 32;
#pragma unroll
        for (int i = 0; i < 8; i++) cp_async16(d + i * 4, src + i);
    };
    auto fillA32 = [&](int seg) {   // f32 source: LDG -> cvt -> STS
        const float4* src = (const float4*)(seg == 0 ? selfp : gatp)
                            + rows[seg] * 32 + ah * 16;
        uint4* d = (uint4*)(smA + arow * PW + ah * 32);
#pragma unroll
        for (int i = 0; i < 8; i++) {
            float4 v0 = __ldg(src + 2 * i), v1 = __ldg(src + 2 * i + 1);
            uint4 w;
            w.x = pack2(v0.x, v0.y); w.y = pack2(v0.z, v0.w);
            w.z = pack2(v1.x, v1.y); w.w = pack2(v1.z, v1.w);
            d[i] = w;
        }
    };
    auto fillB = [&](const uint32_t* src) {   // weight image: cp.async
        const uint4* s = (const uint4*)src;
#pragma unroll
        for (int i = 0; i < 8; i++)
            cp_async16((uint4*)smB + t + i * 256, s + t + i * 256);
        if (t < 128)
            cp_async16((uint4*)smB + 2048 + t, s + 2048 + t);
    };

    // gemm: per k-step load 2 A-ldm x4, then per nh load one B-ldm x4 and
    // consume it immediately (keeps live regs ~80 -> fits the 84-reg cap)
    auto gemm = [&]() {
#pragma unroll
        for (int k = 0; k < 8; k++) {
            uint32_t a[2][4];
#pragma unroll
            for (int mt = 0; mt < 2; mt++)
                asm volatile(
                    "ldmatrix.sync.aligned.m8n8.x4.shared.b16 {%0,%1,%2,%3}, [%4];"
                    : "=r"(a[mt][0]), "=r"(a[mt][1]), "=r"(a[mt][2]), "=r"(a[mt][3])
                    : "r"(Aaddr + aLane + mt * 4352 + k * 32));
#pragma unroll
            for (int nh = 0; nh < 4; nh++) {
                uint32_t b0, b1r, b2r, b3;
                asm volatile(
                    "ldmatrix.sync.aligned.m8n8.x4.shared.b16 {%0,%1,%2,%3}, [%4];"
                    : "=r"(b0), "=r"(b1r), "=r"(b2r), "=r"(b3)
                    : "r"(Baddr + bLane + nh * 4352 + k * 32));
                mma_fp16(accf[0][2*nh],   a[0][0], a[0][1], a[0][2], a[0][3], b0,  b1r);
                mma_fp16(accf[0][2*nh+1], a[0][0], a[0][1], a[0][2], a[0][3], b2r, b3);
                mma_fp16(accf[1][2*nh],   a[1][0], a[1][1], a[1][2], a[1][3], b0,  b1r);
                mma_fp16(accf[1][2*nh+1], a[1][0], a[1][1], a[1][2], a[1][3], b2r, b3);
            }
        }
    };

    // ---- Phase 1: D = X @ W1 over NSEG K-segments of 128 ----
#pragma unroll
    for (int seg = 0; seg < NSEG; seg++) {
        fillB(WB1 + (size_t)seg * TILE_WORDS);
        if (seg == 0) { if (SELF16) fillA16(0); else fillA32(0); }
        else          { if (GAT16)  fillA16(seg); else fillA32(seg); }
        CP_COMMIT();
        CP_WAIT_0();
        __syncthreads();            // tiles ready
        gemm();
        __syncthreads();            // all warps done reading before refill
    }

    // ---- W2 prefetch overlaps H writeback ----
    fillB(WB2);
    CP_COMMIT();
    {
#pragma unroll
        for (int nt = 0; nt < 8; nt++) {
            int col = wn + nt * 8 + 2 * tg;
            float bx = __ldg(&b1[col]), by = __ldg(&b1[col + 1]);
            int wc = col >> 1;
#pragma unroll
            for (int mt = 0; mt < 2; mt++) {
                int row = wm + mt * 16 + g;
                smA[row * PW + wc] =
                    pack2(fast_tanh(accf[mt][nt][0] + bx),
                          fast_tanh(accf[mt][nt][1] + by));
                smA[(row + 8) * PW + wc] =
                    pack2(fast_tanh(accf[mt][nt][2] + bx),
                          fast_tanh(accf[mt][nt][3] + by));
                accf[mt][nt][0] = 0.f; accf[mt][nt][1] = 0.f;
                accf[mt][nt][2] = 0.f; accf[mt][nt][3] = 0.f;
            }
        }
    }
    CP_WAIT_0();
    __syncthreads();

    // ---- Phase 2: Y = H @ W2 ----
    gemm();

    // ---- epilogue: bias2 + (scatter | fp16 store | f32 store) ----
#pragma unroll
    for (int mt = 0; mt < 2; mt++) {
        long ga = r0 + wm + mt * 16 + g;    // rows ga, ga+8
        if (SCATTER) {
            float* dst = (float*)outp;
            int2 pa = __ldg((const int2*)idxs + ga);
            int2 pb = __ldg((const int2*)idxs + ga + 8);
#pragma unroll
            for (int nt = 0; nt < 8; nt++) {
                int col = wn + nt * 8 + 2 * tg;
                float bx = __ldg(&b2[col]), by = __ldg(&b2[col + 1]);
                float x0 = accf[mt][nt][0] + bx, y0 = accf[mt][nt][1] + by;
                float x1 = accf[mt][nt][2] + bx, y1 = accf[mt][nt][3] + by;
                red_add_v2(dst + (long)pa.x * U + col, x0, y0);
                red_add_v2(dst + (long)pa.y * U + col, x0, y0);
                red_add_v2(dst + (long)pb.x * U + col, x1, y1);
                red_add_v2(dst + (long)pb.y * U + col, x1, y1);
            }
        } else if (OUT16) {
            uint32_t* dst = (uint32_t*)outp;
#pragma unroll
            for (int nt = 0; nt < 8; nt++) {
                int col = wn + nt * 8 + 2 * tg;
                float bx = __ldg(&b2[col]), by = __ldg(&b2[col + 1]);
                dst[ga * 64 + (col >> 1)] =
                    pack2(accf[mt][nt][0] + bx, accf[mt][nt][1] + by);
                dst[(ga + 8) * 64 + (col >> 1)] =
                    pack2(accf[mt][nt][2] + bx, accf[mt][nt][3] + by);
            }
        } else {
            float* dst = (float*)outp;
#pragma unroll
            for (int nt = 0; nt < 8; nt++) {
                int col = wn + nt * 8 + 2 * tg;
                float bx = __ldg(&b2[col]), by = __ldg(&b2[col + 1]);
                *(float2*)&dst[ga * U + col] =
                    make_float2(accf[mt][nt][0] + bx, accf[mt][nt][1] + by);
                *(float2*)&dst[(ga + 8) * U + col] =
                    make_float2(accf[mt][nt][2] + bx, accf[mt][nt][3] + by);
            }
        }
    }
}

// ---------------------------------------------------------------------------
// Launch sequence: prep(1), zero_all(2), then 6 MLPs
// ---------------------------------------------------------------------------
extern "C" void kernel_launch(void* const* d_in, const int* in_sizes, int n_in,
                              void* d_out, int out_size)
{
    const float* h1 = (const float*)d_in[0];
    const float* h2 = (const float*)d_in[1];
    const float* h3 = (const float*)d_in[2];
    const float* h4 = (const float*)d_in[3];
    const int* idx2 = (const int*)d_in[4];
    const int* idx3 = (const int*)d_in[5];
    const int* idx4 = (const int*)d_in[6];

    const float* up2W1 = (const float*)d_in[7],  *up2b1 = (const float*)d_in[8],
               * up2W2 = (const float*)d_in[9],  *up2b2 = (const float*)d_in[10];
    const float* up3W1 = (const float*)d_in[11], *up3b1 = (const float*)d_in[12],
               * up3W2 = (const float*)d_in[13], *up3b2 = (const float*)d_in[14];
    const float* up4W1 = (const float*)d_in[15], *up4b1 = (const float*)d_in[16],
               * up4W2 = (const float*)d_in[17], *up4b2 = (const float*)d_in[18];
    const float* dn1W1 = (const float*)d_in[19], *dn1b1 = (const float*)d_in[20],
               * dn1W2 = (const float*)d_in[21], *dn1b2 = (const float*)d_in[22];
    const float* dn2W1 = (const float*)d_in[23], *dn2b1 = (const float*)d_in[24],
               * dn2W2 = (const float*)d_in[25], *dn2b2 = (const float*)d_in[26];
    const float* dn3W1 = (const float*)d_in[27], *dn3b1 = (const float*)d_in[28],
               * dn3W2 = (const float*)d_in[29], *dn3b2 = (const float*)d_in[30];

    float* out = (float*)d_out;

    uint32_t *H2h, *H3h, *WT;
    float *HD3, *HD2, *HD1;
    cudaGetSymbolAddress((void**)&H2h, g_H2h);
    cudaGetSymbolAddress((void**)&H3h, g_H3h);
    cudaGetSymbolAddress((void**)&HD3, g_HD3);
    cudaGetSymbolAddress((void**)&HD2, g_HD2);
    cudaGetSymbolAddress((void**)&HD1, g_HD1);
    cudaGetSymbolAddress((void**)&WT,  g_WT);

    const size_t SMEM = (size_t)2 * TILE_WORDS * 4;   // 69632 B -> 3 CTAs/SM
    cudaFuncSetAttribute((const void*)mlp3<3,false,false,false,true >, cudaFuncAttributeMaxDynamicSharedMemorySize, (int)SMEM);
    cudaFuncSetAttribute((const void*)mlp3<3,false,false,true, true >, cudaFuncAttributeMaxDynamicSharedMemorySize, (int)SMEM);
    cudaFuncSetAttribute((const void*)mlp3<3,true, false,true, false>, cudaFuncAttributeMaxDynamicSharedMemorySize, (int)SMEM);
    cudaFuncSetAttribute((const void*)mlp3<2,true, true, false,false>, cudaFuncAttributeMaxDynamicSharedMemorySize, (int)SMEM);
    cudaFuncSetAttribute((const void*)mlp3<2,false,false,false,false>, cudaFuncAttributeMaxDynamicSharedMemorySize, (int)SMEM);

    // ---- single weight-prep launch ----
    {
        PrepPtrs pp;
        const float* w1s[6] = {up2W1, up3W1, up4W1, dn3W1, dn2W1, dn1W1};
        const int   nch[6]  = {3, 3, 3, 2, 2, 2};
        int c = 0;
        for (int s = 0; s < 6; s++)
            for (int j = 0; j < nch[s]; j++) pp.p[c++] = w1s[s] + (size_t)j * 16384;
        const float* w2s[6] = {up2W2, up3W2, up4W2, dn3W2, dn2W2, dn1W2};
        for (int s = 0; s < 6; s++) pp.p[c++] = w2s[s];
        prep_all<<<(21 * TILE_WORDS + 255) / 256, 256>>>(pp, WT);
    }

    // ---- single zero launch (scatter targets) ----
    {
        long tot = (long)(N3 + N2 + N1) * 32;
        zero_all<<<(int)((tot + 255) / 256), 256>>>((float4*)HD3, (float4*)HD2,
                                                    (float4*)HD1);
    }

    const int g1 = N1 / 128, g2 = N2 / 128, g3 = N3 / 128, g4 = N4 / 128;

    // ---- upward pass ----
    mlp3<3,false,false,false,true ><<<g2, NTHR, SMEM>>>(
        h2, h1, idx2, WT + (size_t)CH_UP2 * TILE_WORDS, up2b1,
        WT + (size_t)CH_W2(0) * TILE_WORDS, up2b2, H2h, nullptr);
    mlp3<3,false,false,true ,true ><<<g3, NTHR, SMEM>>>(
        h3, H2h, idx3, WT + (size_t)CH_UP3 * TILE_WORDS, up3b1,
        WT + (size_t)CH_W2(1) * TILE_WORDS, up3b2, H3h, nullptr);
    mlp3<3,true ,false,true ,false><<<g4, NTHR, SMEM>>>(
        h4, H3h, idx4, WT + (size_t)CH_UP4 * TILE_WORDS, up4b1,
        WT + (size_t)CH_W2(2) * TILE_WORDS, up4b2, HD3, idx4);

    // ---- downward pass ----
    mlp3<2,true ,true ,false,false><<<g3, NTHR, SMEM>>>(
        H3h, HD3, nullptr, WT + (size_t)CH_DN3 * TILE_WORDS, dn3b1,
        WT + (size_t)CH_W2(3) * TILE_WORDS, dn3b2, HD2, idx3);
    mlp3<2,true ,true ,false,false><<<g2, NTHR, SMEM>>>(
        H2h, HD2, nullptr, WT + (size_t)CH_DN2 * TILE_WORDS, dn2b1,
        WT + (size_t)CH_W2(4) * TILE_WORDS, dn2b2, HD1, idx2);
    mlp3<2,false,false,false,false><<<g1, NTHR, SMEM>>>(
        h1, HD1, nullptr, WT + (size_t)CH_DN1 * TILE_WORDS, dn1b1,
        WT + (size_t)CH_W2(5) * TILE_WORDS, dn1b2, out, nullptr);
}

// round 15
// speedup vs baseline: 1.9076x; 1.9076x over previous
#include <cuda_runtime.h>
#include <cuda_fp16.h>
#include <math.h>
#include <stdint.h>

// Problem constants
#define N1 400000
#define N2 400000
#define N3 800000
#define N4 1200000
#define U  128
#define NTHR 256     // 8 warps, 4m x 2n, warp tile 32x64; 2 CTAs/SM
#define PW  68       // tile pitch in half2 words (64 data + 4 pad)
#define TILE_WORDS 8704   // 128 rows x 68 words

// ---------------------------------------------------------------------------
// Scratch buffers
// ---------------------------------------------------------------------------
__device__ uint32_t g_H2h[(size_t)N2 * 64];   // fp16 half2 rows
__device__ uint32_t g_H3h[(size_t)N3 * 64];
__device__ float    g_HD3[(size_t)N3 * U];
__device__ float    g_HD2[(size_t)N2 * U];
__device__ float    g_HD1[(size_t)N1 * U];
// 21 weight chunk images (n-major: word[n*68+k2] = half2(k=2k2,2k2+1) at col n)
__device__ uint32_t g_WT[21 * TILE_WORDS];

#define CH_UP2 0
#define CH_UP3 3
#define CH_UP4 6
#define CH_DN3 9
#define CH_DN2 11
#define CH_DN1 13
#define CH_W2(i) (15 + (i))

// ---------------------------------------------------------------------------
// helpers
// ---------------------------------------------------------------------------
__device__ __forceinline__ float fast_tanh(float x) {
    float e = __expf(2.0f * x);
    return 1.0f - __fdividef(2.0f, e + 1.0f);
}
__device__ __forceinline__ uint32_t h2bits(__half2 h) { return *(uint32_t*)&h; }
__device__ __forceinline__ uint32_t pack2(float x, float y) {
    return h2bits(__floats2half2_rn(x, y));
}
__device__ __forceinline__ void cp_async16(void* dst_smem, const void* src) {
    uint32_t d = (uint32_t)__cvta_generic_to_shared(dst_smem);
    asm volatile("cp.async.cg.shared.global [%0], [%1], 16;" :: "r"(d), "l"(src));
}
#define CP_COMMIT() asm volatile("cp.async.commit_group;" ::: "memory")
#define CP_WAIT_0() asm volatile("cp.async.wait_group 0;" ::: "memory")

__device__ __forceinline__ void red_add_v2(float* p, float x, float y) {
    asm volatile("red.global.add.v2.f32 [%0], {%1,%2};"
                 :: "l"(p), "f"(x), "f"(y) : "memory");
}
__device__ __forceinline__ void mma_fp16(float c[4],
                                         uint32_t a0, uint32_t a1, uint32_t a2, uint32_t a3,
                                         uint32_t b0, uint32_t b1) {
    asm volatile(
        "mma.sync.aligned.m16n8k16.row.col.f32.f16.f16.f32 "
        "{%0,%1,%2,%3}, {%4,%5,%6,%7}, {%8,%9}, {%0,%1,%2,%3};"
        : "+f"(c[0]), "+f"(c[1]), "+f"(c[2]), "+f"(c[3])
        : "r"(a0), "r"(a1), "r"(a2), "r"(a3), "r"(b0), "r"(b1));
}

// ---------------------------------------------------------------------------
// Weight prep (one launch): 21 chunks -> n-major fp16 tile images.
// ---------------------------------------------------------------------------
struct PrepPtrs { const float* p[21]; };

__global__ void prep_all(PrepPtrs pp, uint32_t* __restrict__ dst)
{
    int e = blockIdx.x * 256 + threadIdx.x;
    if (e >= 21 * TILE_WORDS) return;
    int chunk = e / TILE_WORDS, w = e - chunk * TILE_WORDS;
    int n = w / PW, k2 = w - n * PW;
    uint32_t v = 0;
    if (k2 < 64) {
        const float* W = pp.p[chunk];
        v = pack2(W[(size_t)(2 * k2) * 128 + n], W[(size_t)(2 * k2 + 1) * 128 + n]);
    }
    dst[e] = v;
}

__global__ void zero_all(float4* __restrict__ hd3, float4* __restrict__ hd2,
                         float4* __restrict__ hd1)
{
    const long Z3 = (long)N3 * 32, Z2 = (long)N2 * 32, Z1 = (long)N1 * 32;
    long i = (long)blockIdx.x * 256 + threadIdx.x;
    if (i >= Z3 + Z2 + Z1) return;
    float4 z = make_float4(0.f, 0.f, 0.f, 0.f);
    if (i < Z3)           hd3[i] = z;
    else if (i < Z3 + Z2) hd2[i - Z3] = z;
    else                  hd1[i - Z3 - Z2] = z;
}

// ---------------------------------------------------------------------------
// fp16 fused gather + MLP (+ fused scatter), mma m16n8k16, 2 CTAs/SM:
//   y[r] = tanh( concat(segments(r)) @ W1 + b1 ) @ W2 + b2
// CTA tile 128x128, 256 threads, 8 warps (4m x 2n), warp tile 32x64.
// A DOUBLE-buffered (fp16 gathers prefetched via cp.async BEFORE the gemm
// that overlaps them), B single-buffered (refilled right after the post-gemm
// sync; ~L2-hit latency exposed). smem = 3 tiles = 104.4KB -> 2 CTAs/SM,
// 128 regs (no spills — round-14 lesson: 64-reg acc tile can't shrink).
// ---------------------------------------------------------------------------
template <int NSEG, bool SCATTER, bool SELF16, bool GAT16, bool OUT16>
__global__ __launch_bounds__(NTHR, 2)
void mlp2(const void* __restrict__ selfp,
          const void* __restrict__ gatp,
          const int*  __restrict__ idxg,
          const uint32_t* __restrict__ WB1,   // NSEG chunk images
          const float* __restrict__ b1,
          const uint32_t* __restrict__ WB2,   // 1 chunk image
          const float* __restrict__ b2,
          void* __restrict__ outp,
          const int* __restrict__ idxs)
{
    extern __shared__ uint32_t smu[];
    uint32_t* Ab[2] = { smu, smu + TILE_WORDS };   // A ping-pong (then H tile)
    uint32_t* smB   = smu + 2 * TILE_WORDS;        // W tile

    const int t    = threadIdx.x;
    const int lane = t & 31;
    const int cw   = t >> 5;            // warp 0..7
    const int g    = lane >> 2;
    const int tg   = lane & 3;
    const int wm   = (cw & 3) * 32;     // 4 m-warps
    const int wn   = (cw >> 2) * 64;    // 2 n-warps
    const long r0  = (long)blockIdx.x * 128;
    const int arow = t >> 1;            // A-fill: 2 threads per row
    const int ah   = t & 1;             // row half

    const uint32_t smemU = (uint32_t)__cvta_generic_to_shared(smu);
    const uint32_t Aaddr[2] = { smemU, smemU + TILE_WORDS * 4 };
    const uint32_t Baddr    = smemU + 2 * TILE_WORDS * 4;

    // ldmatrix lane offsets (bytes) — layout verified rounds 10-13
    const uint32_t aLane = ((wm + (lane & 15)) * PW + (lane >> 4) * 4) * 4;
    const uint32_t bLane = ((wn + (lane & 7) + ((lane >> 4) << 3)) * PW
                            + ((lane >> 3) & 1) * 4) * 4;

    // gather row indices
    long rows[3];
    rows[0] = r0 + arow;
    if (NSEG == 3) {
        int2 gi = __ldg((const int2*)idxg + (r0 + arow));
        rows[1] = gi.x; rows[2] = gi.y;
    } else {
        rows[1] = r0 + arow;
    }

    float accf[2][8][4];
#pragma unroll
    for (int mt = 0; mt < 2; mt++)
#pragma unroll
        for (int nt = 0; nt < 8; nt++)
#pragma unroll
            for (int c = 0; c < 4; c++) accf[mt][nt][c] = 0.f;

    // ---- fill helpers ----
    auto fillA16 = [&](int seg, uint32_t* dstA) {   // fp16 source: pure cp.async
        const uint4* src = (const uint4*)(seg == 0 ? selfp : gatp)
                           + rows[seg] * 16 + ah * 8;
        uint32_t* d = dstA + arow * PW + ah * 32;
#pragma unroll
        for (int i = 0; i < 8; i++) cp_async16(d + i * 4, src + i);
    };
    auto fillA32 = [&](int seg, uint32_t* dstA) {   // f32 source: LDG->cvt->STS
        const float4* src = (const float4*)(seg == 0 ? selfp : gatp)
                            + rows[seg] * 32 + ah * 16;
        uint4* d = (uint4*)(dstA + arow * PW + ah * 32);
#pragma unroll
        for (int i = 0; i < 8; i++) {
            float4 v0 = __ldg(src + 2 * i), v1 = __ldg(src + 2 * i + 1);
            uint4 w;
            w.x = pack2(v0.x, v0.y); w.y = pack2(v0.z, v0.w);
            w.z = pack2(v1.x, v1.y); w.w = pack2(v1.z, v1.w);
            d[i] = w;
        }
    };
    auto fillB = [&](const uint32_t* src) {         // weight image: cp.async
        const uint4* s = (const uint4*)src;
#pragma unroll
        for (int i = 0; i < 8; i++)
            cp_async16((uint4*)smB + t + i * 256, s + t + i * 256);
        if (t < 128)
            cp_async16((uint4*)smB + 2048 + t, s + 2048 + t);
    };

    auto gemm = [&](uint32_t Aa) {
#pragma unroll
        for (int k = 0; k < 8; k++) {
            uint32_t a[2][4], b[8][2];
#pragma unroll
            for (int mt = 0; mt < 2; mt++)
                asm volatile(
                    "ldmatrix.sync.aligned.m8n8.x4.shared.b16 {%0,%1,%2,%3}, [%4];"
                    : "=r"(a[mt][0]), "=r"(a[mt][1]), "=r"(a[mt][2]), "=r"(a[mt][3])
                    : "r"(Aa + aLane + mt * 4352 + k * 32));
#pragma unroll
            for (int nh = 0; nh < 4; nh++)
                asm volatile(
                    "ldmatrix.sync.aligned.m8n8.x4.shared.b16 {%0,%1,%2,%3}, [%4];"
                    : "=r"(b[2*nh][0]), "=r"(b[2*nh][1]),
                      "=r"(b[2*nh+1][0]), "=r"(b[2*nh+1][1])
                    : "r"(Baddr + bLane + nh * 4352 + k * 32));
#pragma unroll
            for (int mt = 0; mt < 2; mt++)
#pragma unroll
                for (int nt = 0; nt < 8; nt++)
                    mma_fp16(accf[mt][nt], a[mt][0], a[mt][1], a[mt][2], a[mt][3],
                             b[nt][0], b[nt][1]);
        }
    };

    // ---- prologue: segment 0 tiles ----
    if (SELF16) fillA16(0, Ab[0]); else fillA32(0, Ab[0]);
    fillB(WB1);
    CP_COMMIT();
    CP_WAIT_0();
    __syncthreads();

    // ---- Phase 1: D = X @ W1 over NSEG K-segments of 128 ----
#pragma unroll
    for (int seg = 0; seg < NSEG; seg++) {
        const bool nextA = (seg + 1 < NSEG);
        // fp16 gathers: prefetch next A tile before the gemm that hides it
        if (nextA && GAT16) {
            fillA16(seg + 1, Ab[(seg + 1) & 1]);
            CP_COMMIT();
        }
        gemm(Aaddr[seg & 1]);
        __syncthreads();            // all warps done reading A(seg), B(seg)
        if (nextA) {
            fillB(WB1 + (size_t)(seg + 1) * TILE_WORDS);
            CP_COMMIT();
            if (!GAT16) fillA32(seg + 1, Ab[(seg + 1) & 1]);
            CP_WAIT_0();
            __syncthreads();
        } else {
            fillB(WB2);             // W2 prefetch; waited after H writeback
            CP_COMMIT();
        }
    }

    // ---- H = fp16(tanh(acc + b1)) -> free A buffer (overlaps W2 fill) ----
    {
        uint32_t* Ah = Ab[NSEG & 1];
#pragma unroll
        for (int nt = 0; nt < 8; nt++) {
            int col = wn + nt * 8 + 2 * tg;
            float bx = __ldg(&b1[col]), by = __ldg(&b1[col + 1]);
            int wc = col >> 1;
#pragma unroll
            for (int mt = 0; mt < 2; mt++) {
                int row = wm + mt * 16 + g;
                Ah[row * PW + wc] =
                    pack2(fast_tanh(accf[mt][nt][0] + bx),
                          fast_tanh(accf[mt][nt][1] + by));
                Ah[(row + 8) * PW + wc] =
                    pack2(fast_tanh(accf[mt][nt][2] + bx),
                          fast_tanh(accf[mt][nt][3] + by));
                accf[mt][nt][0] = 0.f; accf[mt][nt][1] = 0.f;
                accf[mt][nt][2] = 0.f; accf[mt][nt][3] = 0.f;
            }
        }
    }
    CP_WAIT_0();
    __syncthreads();

    // ---- Phase 2: Y = H @ W2 ----
    gemm(Aaddr[NSEG & 1]);

    // ---- epilogue: bias2 + (scatter | fp16 store | f32 store) ----
    float bx[8], by[8];
#pragma unroll
    for (int nt = 0; nt < 8; nt++) {
        int col = wn + nt * 8 + 2 * tg;
        bx[nt] = __ldg(&b2[col]);
        by[nt] = __ldg(&b2[col + 1]);
    }
#pragma unroll
    for (int mt = 0; mt < 2; mt++) {
        long ga = r0 + wm + mt * 16 + g;    // rows ga, ga+8
        if (SCATTER) {
            float* dst = (float*)outp;
            int2 pa = __ldg((const int2*)idxs + ga);
            int2 pb = __ldg((const int2*)idxs + ga + 8);
#pragma unroll
            for (int nt = 0; nt < 8; nt++) {
                int col = wn + nt * 8 + 2 * tg;
                float x0 = accf[mt][nt][0] + bx[nt], y0 = accf[mt][nt][1] + by[nt];
                float x1 = accf[mt][nt][2] + bx[nt], y1 = accf[mt][nt][3] + by[nt];
                red_add_v2(dst + (long)pa.x * U + col, x0, y0);
                red_add_v2(dst + (long)pa.y * U + col, x0, y0);
                red_add_v2(dst + (long)pb.x * U + col, x1, y1);
                red_add_v2(dst + (long)pb.y * U + col, x1, y1);
            }
        } else if (OUT16) {
            uint32_t* dst = (uint32_t*)outp;
#pragma unroll
            for (int nt = 0; nt < 8; nt++) {
                int col = wn + nt * 8 + 2 * tg;
                dst[ga * 64 + (col >> 1)] =
                    pack2(accf[mt][nt][0] + bx[nt], accf[mt][nt][1] + by[nt]);
                dst[(ga + 8) * 64 + (col >> 1)] =
                    pack2(accf[mt][nt][2] + bx[nt], accf[mt][nt][3] + by[nt]);
            }
        } else {
            float* dst = (float*)outp;
#pragma unroll
            for (int nt = 0; nt < 8; nt++) {
                int col = wn + nt * 8 + 2 * tg;
                *(float2*)&dst[ga * U + col] =
                    make_float2(accf[mt][nt][0] + bx[nt], accf[mt][nt][1] + by[nt]);
                *(float2*)&dst[(ga + 8) * U + col] =
                    make_float2(accf[mt][nt][2] + bx[nt], accf[mt][nt][3] + by[nt]);
            }
        }
    }
}

// ---------------------------------------------------------------------------
// Launch sequence: prep(1), zero_all(2), then 6 MLPs
// ---------------------------------------------------------------------------
extern "C" void kernel_launch(void* const* d_in, const int* in_sizes, int n_in,
                              void* d_out, int out_size)
{
    const float* h1 = (const float*)d_in[0];
    const float* h2 = (const float*)d_in[1];
    const float* h3 = (const float*)d_in[2];
    const float* h4 = (const float*)d_in[3];
    const int* idx2 = (const int*)d_in[4];
    const int* idx3 = (const int*)d_in[5];
    const int* idx4 = (const int*)d_in[6];

    const float* up2W1 = (const float*)d_in[7],  *up2b1 = (const float*)d_in[8],
               * up2W2 = (const float*)d_in[9],  *up2b2 = (const float*)d_in[10];
    const float* up3W1 = (const float*)d_in[11], *up3b1 = (const float*)d_in[12],
               * up3W2 = (const float*)d_in[13], *up3b2 = (const float*)d_in[14];
    const float* up4W1 = (const float*)d_in[15], *up4b1 = (const float*)d_in[16],
               * up4W2 = (const float*)d_in[17], *up4b2 = (const float*)d_in[18];
    const float* dn1W1 = (const float*)d_in[19], *dn1b1 = (const float*)d_in[20],
               * dn1W2 = (const float*)d_in[21], *dn1b2 = (const float*)d_in[22];
    const float* dn2W1 = (const float*)d_in[23], *dn2b1 = (const float*)d_in[24],
               * dn2W2 = (const float*)d_in[25], *dn2b2 = (const float*)d_in[26];
    const float* dn3W1 = (const float*)d_in[27], *dn3b1 = (const float*)d_in[28],
               * dn3W2 = (const float*)d_in[29], *dn3b2 = (const float*)d_in[30];

    float* out = (float*)d_out;

    uint32_t *H2h, *H3h, *WT;
    float *HD3, *HD2, *HD1;
    cudaGetSymbolAddress((void**)&H2h, g_H2h);
    cudaGetSymbolAddress((void**)&H3h, g_H3h);
    cudaGetSymbolAddress((void**)&HD3, g_HD3);
    cudaGetSymbolAddress((void**)&HD2, g_HD2);
    cudaGetSymbolAddress((void**)&HD1, g_HD1);
    cudaGetSymbolAddress((void**)&WT,  g_WT);

    const size_t SMEM = (size_t)3 * TILE_WORDS * 4;   // 104448 B -> 2 CTAs/SM
    cudaFuncSetAttribute((const void*)mlp2<3,false,false,false,true >, cudaFuncAttributeMaxDynamicSharedMemorySize, (int)SMEM);
    cudaFuncSetAttribute((const void*)mlp2<3,false,false,true, true >, cudaFuncAttributeMaxDynamicSharedMemorySize, (int)SMEM);
    cudaFuncSetAttribute((const void*)mlp2<3,true, false,true, false>, cudaFuncAttributeMaxDynamicSharedMemorySize, (int)SMEM);
    cudaFuncSetAttribute((const void*)mlp2<2,true, true, false,false>, cudaFuncAttributeMaxDynamicSharedMemorySize, (int)SMEM);
    cudaFuncSetAttribute((const void*)mlp2<2,false,false,false,false>, cudaFuncAttributeMaxDynamicSharedMemorySize, (int)SMEM);

    // ---- single weight-prep launch ----
    {
        PrepPtrs pp;
        const float* w1s[6] = {up2W1, up3W1, up4W1, dn3W1, dn2W1, dn1W1};
        const int   nch[6]  = {3, 3, 3, 2, 2, 2};
        int c = 0;
        for (int s = 0; s < 6; s++)
            for (int j = 0; j < nch[s]; j++) pp.p[c++] = w1s[s] + (size_t)j * 16384;
        const float* w2s[6] = {up2W2, up3W2, up4W2, dn3W2, dn2W2, dn1W2};
        for (int s = 0; s < 6; s++) pp.p[c++] = w2s[s];
        prep_all<<<(21 * TILE_WORDS + 255) / 256, 256>>>(pp, WT);
    }

    // ---- single zero launch (scatter targets) ----
    {
        long tot = (long)(N3 + N2 + N1) * 32;
        zero_all<<<(int)((tot + 255) / 256), 256>>>((float4*)HD3, (float4*)HD2,
                                                    (float4*)HD1);
    }

    const int g1 = N1 / 128, g2 = N2 / 128, g3 = N3 / 128, g4 = N4 / 128;

    // ---- upward pass ----
    mlp2<3,false,false,false,true ><<<g2, NTHR, SMEM>>>(
        h2, h1, idx2, WT + (size_t)CH_UP2 * TILE_WORDS, up2b1,
        WT + (size_t)CH_W2(0) * TILE_WORDS, up2b2, H2h, nullptr);
    mlp2<3,false,false,true ,true ><<<g3, NTHR, SMEM>>>(
        h3, H2h, idx3, WT + (size_t)CH_UP3 * TILE_WORDS, up3b1,
        WT + (size_t)CH_W2(1) * TILE_WORDS, up3b2, H3h, nullptr);
    mlp2<3,true ,false,true ,false><<<g4, NTHR, SMEM>>>(
        h4, H3h, idx4, WT + (size_t)CH_UP4 * TILE_WORDS, up4b1,
        WT + (size_t)CH_W2(2) * TILE_WORDS, up4b2, HD3, idx4);

    // ---- downward pass ----
    mlp2<2,true ,true ,false,false><<<g3, NTHR, SMEM>>>(
        H3h, HD3, nullptr, WT + (size_t)CH_DN3 * TILE_WORDS, dn3b1,
        WT + (size_t)CH_W2(3) * TILE_WORDS, dn3b2, HD2, idx3);
    mlp2<2,true ,true ,false,false><<<g2, NTHR, SMEM>>>(
        H2h, HD2, nullptr, WT + (size_t)CH_DN2 * TILE_WORDS, dn2b1,
        WT + (size_t)CH_W2(4) * TILE_WORDS, dn2b2, HD1, idx2);
    mlp2<2,false,false,false,false><<<g1, NTHR, SMEM>>>(
        h1, HD1, nullptr, WT + (size_t)CH_DN1 * TILE_WORDS, dn1b1,
        WT + (size_t)CH_W2(5) * TILE_WORDS, dn1b2, out, nullptr);
}

// round 16
// speedup vs baseline: 2.2797x; 1.1951x over previous
#include <cuda_runtime.h>
#include <cuda_fp16.h>
#include <math.h>
#include <stdint.h>

// Problem constants
#define N1 400000
#define N2 400000
#define N3 800000
#define N4 1200000
#define U  128
#define NTHR 256     // 8 warps, 4m x 2n, warp tile 32x64; 2 CTAs/SM
#define PW  68       // tile pitch in half2 words (64 data + 4 pad)
#define TILE_WORDS 8704   // 128 rows x 68 words

// ---------------------------------------------------------------------------
// Scratch buffers
// ---------------------------------------------------------------------------
__device__ uint32_t g_H2h[(size_t)N2 * 64];   // fp16 half2 rows
__device__ uint32_t g_H3h[(size_t)N3 * 64];
__device__ float    g_HD3[(size_t)N3 * U];
__device__ float    g_HD2[(size_t)N2 * U];
__device__ float    g_HD1[(size_t)N1 * U];
// 21 weight chunk images (n-major: word[n*68+k2] = half2(k=2k2,2k2+1) at col n)
__device__ uint32_t g_WT[21 * TILE_WORDS];

#define CH_UP2 0
#define CH_UP3 3
#define CH_UP4 6
#define CH_DN3 9
#define CH_DN2 11
#define CH_DN1 13
#define CH_W2(i) (15 + (i))

// ---------------------------------------------------------------------------
// helpers
// ---------------------------------------------------------------------------
__device__ __forceinline__ float fast_tanh(float x) {
    float e = __expf(2.0f * x);
    return 1.0f - __fdividef(2.0f, e + 1.0f);
}
__device__ __forceinline__ uint32_t h2bits(__half2 h) { return *(uint32_t*)&h; }
__device__ __forceinline__ uint32_t pack2(float x, float y) {
    return h2bits(__floats2half2_rn(x, y));
}
__device__ __forceinline__ void cp_async16(void* dst_smem, const void* src) {
    uint32_t d = (uint32_t)__cvta_generic_to_shared(dst_smem);
    asm volatile("cp.async.cg.shared.global [%0], [%1], 16;" :: "r"(d), "l"(src));
}
#define CP_COMMIT() asm volatile("cp.async.commit_group;" ::: "memory")
#define CP_WAIT_0() asm volatile("cp.async.wait_group 0;" ::: "memory")

__device__ __forceinline__ void prefetch_l2(const void* p) {
    asm volatile("prefetch.global.L2 [%0];" :: "l"(p));
}
__device__ __forceinline__ void red_add_v2(float* p, float x, float y) {
    asm volatile("red.global.add.v2.f32 [%0], {%1,%2};"
                 :: "l"(p), "f"(x), "f"(y) : "memory");
}
__device__ __forceinline__ void mma_fp16(float c[4],
                                         uint32_t a0, uint32_t a1, uint32_t a2, uint32_t a3,
                                         uint32_t b0, uint32_t b1) {
    asm volatile(
        "mma.sync.aligned.m16n8k16.row.col.f32.f16.f16.f32 "
        "{%0,%1,%2,%3}, {%4,%5,%6,%7}, {%8,%9}, {%0,%1,%2,%3};"
        : "+f"(c[0]), "+f"(c[1]), "+f"(c[2]), "+f"(c[3])
        : "r"(a0), "r"(a1), "r"(a2), "r"(a3), "r"(b0), "r"(b1));
}

// ---------------------------------------------------------------------------
// Weight prep (one launch): 21 chunks -> n-major fp16 tile images.
// ---------------------------------------------------------------------------
struct PrepPtrs { const float* p[21]; };

__global__ void prep_all(PrepPtrs pp, uint32_t* __restrict__ dst)
{
    int e = blockIdx.x * 256 + threadIdx.x;
    if (e >= 21 * TILE_WORDS) return;
    int chunk = e / TILE_WORDS, w = e - chunk * TILE_WORDS;
    int n = w / PW, k2 = w - n * PW;
    uint32_t v = 0;
    if (k2 < 64) {
        const float* W = pp.p[chunk];
        v = pack2(W[(size_t)(2 * k2) * 128 + n], W[(size_t)(2 * k2 + 1) * 128 + n]);
    }
    dst[e] = v;
}

__global__ void zero_all(float4* __restrict__ hd3, float4* __restrict__ hd2,
                         float4* __restrict__ hd1)
{
    const long Z3 = (long)N3 * 32, Z2 = (long)N2 * 32, Z1 = (long)N1 * 32;
    long i = (long)blockIdx.x * 256 + threadIdx.x;
    if (i >= Z3 + Z2 + Z1) return;
    float4 z = make_float4(0.f, 0.f, 0.f, 0.f);
    if (i < Z3)           hd3[i] = z;
    else if (i < Z3 + Z2) hd2[i - Z3] = z;
    else                  hd1[i - Z3 - Z2] = z;
}

// ---------------------------------------------------------------------------
// fp16 fused gather + MLP (+ fused scatter), mma m16n8k16, 2 CTAs/SM:
//   y[r] = tanh( concat(segments(r)) @ W1 + b1 ) @ W2 + b2
// CTA tile 128x128, 256 threads, 8 warps (4m x 2n), warp tile 32x64.
// A and B single-buffered (69.6KB smem -> 2 CTAs/SM). Round-13 structure,
// plus: (1) segment order rotated by CTA parity to break the co-resident-CTA
// convoy; (2) prefetch.global.L2 of the NEXT segment's gather rows issued
// before each gemm — L2-only warming (no L1 contention, the round-15 lesson).
// ---------------------------------------------------------------------------
template <int NSEG, bool SCATTER, bool SELF16, bool GAT16, bool OUT16>
__global__ __launch_bounds__(NTHR, 2)
void mlp2(const void* __restrict__ selfp,
          const void* __restrict__ gatp,
          const int*  __restrict__ idxg,
          const uint32_t* __restrict__ WB1,   // NSEG chunk images
          const float* __restrict__ b1,
          const uint32_t* __restrict__ WB2,   // 1 chunk image
          const float* __restrict__ b2,
          void* __restrict__ outp,
          const int* __restrict__ idxs)
{
    extern __shared__ uint32_t smu[];
    uint32_t* smA = smu;                // A tile (then H tile)
    uint32_t* smB = smu + TILE_WORDS;   // W tile

    const int t    = threadIdx.x;
    const int lane = t & 31;
    const int cw   = t >> 5;            // warp 0..7
    const int g    = lane >> 2;
    const int tg   = lane & 3;
    const int wm   = (cw & 3) * 32;     // 4 m-warps
    const int wn   = (cw >> 2) * 64;    // 2 n-warps
    const long r0  = (long)blockIdx.x * 128;
    const int arow = t >> 1;            // A-fill: 2 threads per row
    const int ah   = t & 1;             // row half
    const int rot  = (int)(blockIdx.x & 1);   // convoy-breaking rotation

    const uint32_t smemU = (uint32_t)__cvta_generic_to_shared(smu);
    const uint32_t Aaddr = smemU;
    const uint32_t Baddr = smemU + TILE_WORDS * 4;

    // ldmatrix lane offsets (bytes) — layout verified rounds 10-13
    const uint32_t aLane = ((wm + (lane & 15)) * PW + (lane >> 4) * 4) * 4;
    const uint32_t bLane = ((wn + (lane & 7) + ((lane >> 4) << 3)) * PW
                            + ((lane >> 3) & 1) * 4) * 4;

    // gather row indices
    long rows[3];
    rows[0] = r0 + arow;
    if (NSEG == 3) {
        int2 gi = __ldg((const int2*)idxg + (r0 + arow));
        rows[1] = gi.x; rows[2] = gi.y;
    } else {
        rows[1] = r0 + arow;
    }

    float accf[2][8][4];
#pragma unroll
    for (int mt = 0; mt < 2; mt++)
#pragma unroll
        for (int nt = 0; nt < 8; nt++)
#pragma unroll
            for (int c = 0; c < 4; c++) accf[mt][nt][c] = 0.f;

    // ---- fill helpers ----
    auto fillA16 = [&](int seg) {   // fp16 source: pure cp.async
        const uint4* src = (const uint4*)(seg == 0 ? selfp : gatp)
                           + rows[seg] * 16 + ah * 8;
        uint32_t* d = smA + arow * PW + ah * 32;
#pragma unroll
        for (int i = 0; i < 8; i++) cp_async16(d + i * 4, src + i);
    };
    auto fillA32 = [&](int seg) {   // f32 source: LDG -> cvt -> STS
        const float4* src = (const float4*)(seg == 0 ? selfp : gatp)
                            + rows[seg] * 32 + ah * 16;
        uint4* d = (uint4*)(smA + arow * PW + ah * 32);
#pragma unroll
        for (int i = 0; i < 8; i++) {
            float4 v0 = __ldg(src + 2 * i), v1 = __ldg(src + 2 * i + 1);
            uint4 w;
            w.x = pack2(v0.x, v0.y); w.y = pack2(v0.z, v0.w);
            w.z = pack2(v1.x, v1.y); w.w = pack2(v1.z, v1.w);
            d[i] = w;
        }
    };
    auto fillB = [&](const uint32_t* src) {   // weight image: cp.async
        const uint4* s = (const uint4*)src;
#pragma unroll
        for (int i = 0; i < 8; i++)
            cp_async16((uint4*)smB + t + i * 256, s + t + i * 256);
        if (t < 128)
            cp_async16((uint4*)smB + 2048 + t, s + 2048 + t);
    };
    // L2-only prefetch of segment seg's gather rows (this thread's region)
    auto prefetchA = [&](int seg) {
        const bool f16 = (seg == 0) ? SELF16 : GAT16;
        const char* base = (const char*)(seg == 0 ? selfp : gatp);
        if (f16) {
            prefetch_l2(base + rows[seg] * 256 + ah * 128);
        } else {
            const char* p = base + rows[seg] * 512 + ah * 256;
            prefetch_l2(p);
            prefetch_l2(p + 128);
        }
    };

    auto gemm = [&]() {
#pragma unroll
        for (int k = 0; k < 8; k++) {
            uint32_t a[2][4], b[8][2];
#pragma unroll
            for (int mt = 0; mt < 2; mt++)
                asm volatile(
                    "ldmatrix.sync.aligned.m8n8.x4.shared.b16 {%0,%1,%2,%3}, [%4];"
                    : "=r"(a[mt][0]), "=r"(a[mt][1]), "=r"(a[mt][2]), "=r"(a[mt][3])
                    : "r"(Aaddr + aLane + mt * 4352 + k * 32));
#pragma unroll
            for (int nh = 0; nh < 4; nh++)
                asm volatile(
                    "ldmatrix.sync.aligned.m8n8.x4.shared.b16 {%0,%1,%2,%3}, [%4];"
                    : "=r"(b[2*nh][0]), "=r"(b[2*nh][1]),
                      "=r"(b[2*nh+1][0]), "=r"(b[2*nh+1][1])
                    : "r"(Baddr + bLane + nh * 4352 + k * 32));
#pragma unroll
            for (int mt = 0; mt < 2; mt++)
#pragma unroll
                for (int nt = 0; nt < 8; nt++)
                    mma_fp16(accf[mt][nt], a[mt][0], a[mt][1], a[mt][2], a[mt][3],
                             b[nt][0], b[nt][1]);
        }
    };

    // ---- Phase 1: D = X @ W1 over NSEG K-segments (rotated per CTA parity) ----
#pragma unroll
    for (int i = 0; i < NSEG; i++) {
        int seg  = i + rot; if (seg >= NSEG) seg -= NSEG;
        fillB(WB1 + (size_t)seg * TILE_WORDS);
        if (seg == 0) { if (SELF16) fillA16(0);   else fillA32(0);   }
        else          { if (GAT16)  fillA16(seg); else fillA32(seg); }
        CP_COMMIT();
        CP_WAIT_0();
        __syncthreads();            // tiles ready
        if (i + 1 < NSEG) {         // warm L2 for the next segment's gathers
            int nseg = i + 1 + rot; if (nseg >= NSEG) nseg -= NSEG;
            prefetchA(nseg);
        }
        gemm();
        __syncthreads();            // all warps done reading before refill
    }

    // ---- W2 prefetch overlaps H writeback ----
    fillB(WB2);
    CP_COMMIT();
    {
#pragma unroll
        for (int nt = 0; nt < 8; nt++) {
            int col = wn + nt * 8 + 2 * tg;
            float bx = __ldg(&b1[col]), by = __ldg(&b1[col + 1]);
            int wc = col >> 1;
#pragma unroll
            for (int mt = 0; mt < 2; mt++) {
                int row = wm + mt * 16 + g;
                smA[row * PW + wc] =
                    pack2(fast_tanh(accf[mt][nt][0] + bx),
                          fast_tanh(accf[mt][nt][1] + by));
                smA[(row + 8) * PW + wc] =
                    pack2(fast_tanh(accf[mt][nt][2] + bx),
                          fast_tanh(accf[mt][nt][3] + by));
                accf[mt][nt][0] = 0.f; accf[mt][nt][1] = 0.f;
                accf[mt][nt][2] = 0.f; accf[mt][nt][3] = 0.f;
            }
        }
    }
    CP_WAIT_0();
    __syncthreads();

    // ---- Phase 2: Y = H @ W2 ----
    gemm();

    // ---- epilogue: bias2 + (scatter | fp16 store | f32 store) ----
    float bx[8], by[8];
#pragma unroll
    for (int nt = 0; nt < 8; nt++) {
        int col = wn + nt * 8 + 2 * tg;
        bx[nt] = __ldg(&b2[col]);
        by[nt] = __ldg(&b2[col + 1]);
    }
#pragma unroll
    for (int mt = 0; mt < 2; mt++) {
        long ga = r0 + wm + mt * 16 + g;    // rows ga, ga+8
        if (SCATTER) {
            float* dst = (float*)outp;
            int2 pa = __ldg((const int2*)idxs + ga);
            int2 pb = __ldg((const int2*)idxs + ga + 8);
#pragma unroll
            for (int nt = 0; nt < 8; nt++) {
                int col = wn + nt * 8 + 2 * tg;
                float x0 = accf[mt][nt][0] + bx[nt], y0 = accf[mt][nt][1] + by[nt];
                float x1 = accf[mt][nt][2] + bx[nt], y1 = accf[mt][nt][3] + by[nt];
                red_add_v2(dst + (long)pa.x * U + col, x0, y0);
                red_add_v2(dst + (long)pa.y * U + col, x0, y0);
                red_add_v2(dst + (long)pb.x * U + col, x1, y1);
                red_add_v2(dst + (long)pb.y * U + col, x1, y1);
            }
        } else if (OUT16) {
            uint32_t* dst = (uint32_t*)outp;
#pragma unroll
            for (int nt = 0; nt < 8; nt++) {
                int col = wn + nt * 8 + 2 * tg;
                dst[ga * 64 + (col >> 1)] =
                    pack2(accf[mt][nt][0] + bx[nt], accf[mt][nt][1] + by[nt]);
                dst[(ga + 8) * 64 + (col >> 1)] =
                    pack2(accf[mt][nt][2] + bx[nt], accf[mt][nt][3] + by[nt]);
            }
        } else {
            float* dst = (float*)outp;
#pragma unroll
            for (int nt = 0; nt < 8; nt++) {
                int col = wn + nt * 8 + 2 * tg;
                *(float2*)&dst[ga * U + col] =
                    make_float2(accf[mt][nt][0] + bx[nt], accf[mt][nt][1] + by[nt]);
                *(float2*)&dst[(ga + 8) * U + col] =
                    make_float2(accf[mt][nt][2] + bx[nt], accf[mt][nt][3] + by[nt]);
            }
        }
    }
}

// ---------------------------------------------------------------------------
// Launch sequence: prep(1), zero_all(2), then 6 MLPs
// ---------------------------------------------------------------------------
extern "C" void kernel_launch(void* const* d_in, const int* in_sizes, int n_in,
                              void* d_out, int out_size)
{
    const float* h1 = (const float*)d_in[0];
    const float* h2 = (const float*)d_in[1];
    const float* h3 = (const float*)d_in[2];
    const float* h4 = (const float*)d_in[3];
    const int* idx2 = (const int*)d_in[4];
    const int* idx3 = (const int*)d_in[5];
    const int* idx4 = (const int*)d_in[6];

    const float* up2W1 = (const float*)d_in[7],  *up2b1 = (const float*)d_in[8],
               * up2W2 = (const float*)d_in[9],  *up2b2 = (const float*)d_in[10];
    const float* up3W1 = (const float*)d_in[11], *up3b1 = (const float*)d_in[12],
               * up3W2 = (const float*)d_in[13], *up3b2 = (const float*)d_in[14];
    const float* up4W1 = (const float*)d_in[15], *up4b1 = (const float*)d_in[16],
               * up4W2 = (const float*)d_in[17], *up4b2 = (const float*)d_in[18];
    const float* dn1W1 = (const float*)d_in[19], *dn1b1 = (const float*)d_in[20],
               * dn1W2 = (const float*)d_in[21], *dn1b2 = (const float*)d_in[22];
    const float* dn2W1 = (const float*)d_in[23], *dn2b1 = (const float*)d_in[24],
               * dn2W2 = (const float*)d_in[25], *dn2b2 = (const float*)d_in[26];
    const float* dn3W1 = (const float*)d_in[27], *dn3b1 = (const float*)d_in[28],
               * dn3W2 = (const float*)d_in[29], *dn3b2 = (const float*)d_in[30];

    float* out = (float*)d_out;

    uint32_t *H2h, *H3h, *WT;
    float *HD3, *HD2, *HD1;
    cudaGetSymbolAddress((void**)&H2h, g_H2h);
    cudaGetSymbolAddress((void**)&H3h, g_H3h);
    cudaGetSymbolAddress((void**)&HD3, g_HD3);
    cudaGetSymbolAddress((void**)&HD2, g_HD2);
    cudaGetSymbolAddress((void**)&HD1, g_HD1);
    cudaGetSymbolAddress((void**)&WT,  g_WT);

    const size_t SMEM = (size_t)2 * TILE_WORDS * 4;   // 69632 B -> 2 CTAs/SM
    cudaFuncSetAttribute((const void*)mlp2<3,false,false,false,true >, cudaFuncAttributeMaxDynamicSharedMemorySize, (int)SMEM);
    cudaFuncSetAttribute((const void*)mlp2<3,false,false,true, true >, cudaFuncAttributeMaxDynamicSharedMemorySize, (int)SMEM);
    cudaFuncSetAttribute((const void*)mlp2<3,true, false,true, false>, cudaFuncAttributeMaxDynamicSharedMemorySize, (int)SMEM);
    cudaFuncSetAttribute((const void*)mlp2<2,true, true, false,false>, cudaFuncAttributeMaxDynamicSharedMemorySize, (int)SMEM);
    cudaFuncSetAttribute((const void*)mlp2<2,false,false,false,false>, cudaFuncAttributeMaxDynamicSharedMemorySize, (int)SMEM);

    // ---- single weight-prep launch ----
    {
        PrepPtrs pp;
        const float* w1s[6] = {up2W1, up3W1, up4W1, dn3W1, dn2W1, dn1W1};
        const int   nch[6]  = {3, 3, 3, 2, 2, 2};
        int c = 0;
        for (int s = 0; s < 6; s++)
            for (int j = 0; j < nch[s]; j++) pp.p[c++] = w1s[s] + (size_t)j * 16384;
        const float* w2s[6] = {up2W2, up3W2, up4W2, dn3W2, dn2W2, dn1W2};
        for (int s = 0; s < 6; s++) pp.p[c++] = w2s[s];
        prep_all<<<(21 * TILE_WORDS + 255) / 256, 256>>>(pp, WT);
    }

    // ---- single zero launch (scatter targets) ----
    {
        long tot = (long)(N3 + N2 + N1) * 32;
        zero_all<<<(int)((tot + 255) / 256), 256>>>((float4*)HD3, (float4*)HD2,
                                                    (float4*)HD1);
    }

    const int g1 = N1 / 128, g2 = N2 / 128, g3 = N3 / 128, g4 = N4 / 128;

    // ---- upward pass ----
    mlp2<3,false,false,false,true ><<<g2, NTHR, SMEM>>>(
        h2, h1, idx2, WT + (size_t)CH_UP2 * TILE_WORDS, up2b1,
        WT + (size_t)CH_W2(0) * TILE_WORDS, up2b2, H2h, nullptr);
    mlp2<3,false,false,true ,true ><<<g3, NTHR, SMEM>>>(
        h3, H2h, idx3, WT + (size_t)CH_UP3 * TILE_WORDS, up3b1,
        WT + (size_t)CH_W2(1) * TILE_WORDS, up3b2, H3h, nullptr);
    mlp2<3,true ,false,true ,false><<<g4, NTHR, SMEM>>>(
        h4, H3h, idx4, WT + (size_t)CH_UP4 * TILE_WORDS, up4b1,
        WT + (size_t)CH_W2(2) * TILE_WORDS, up4b2, HD3, idx4);

    // ---- downward pass ----
    mlp2<2,true ,true ,false,false><<<g3, NTHR, SMEM>>>(
        H3h, HD3, nullptr, WT + (size_t)CH_DN3 * TILE_WORDS, dn3b1,
        WT + (size_t)CH_W2(3) * TILE_WORDS, dn3b2, HD2, idx3);
    mlp2<2,true ,true ,false,false><<<g2, NTHR, SMEM>>>(
        H2h, HD2, nullptr, WT + (size_t)CH_DN2 * TILE_WORDS, dn2b1,
        WT + (size_t)CH_W2(4) * TILE_WORDS, dn2b2, HD1, idx2);
    mlp2<2,false,false,false,false><<<g1, NTHR, SMEM>>>(
        h1, HD1, nullptr, WT + (size_t)CH_DN1 * TILE_WORDS, dn1b1,
        WT + (size_t)CH_W2(5) * TILE_WORDS, dn1b2, out, nullptr);
}

// round 17
// speedup vs baseline: 2.3199x; 1.0176x over previous
#include <cuda_runtime.h>
#include <cuda_fp16.h>
#include <math.h>
#include <stdint.h>

// Problem constants
#define N1 400000
#define N2 400000
#define N3 800000
#define N4 1200000
#define U  128
#define NTHR 256     // 8 warps, 4m x 2n, warp tile 32x64; 2 CTAs/SM
#define PW  68       // tile pitch in half2 words (64 data + 4 pad)
#define TILE_WORDS 8704   // 128 rows x 68 words

// ---------------------------------------------------------------------------
// Scratch buffers
// ---------------------------------------------------------------------------
__device__ uint32_t g_H2h[(size_t)N2 * 64];   // fp16 half2 rows
__device__ uint32_t g_H3h[(size_t)N3 * 64];
__device__ float    g_HD3[(size_t)N3 * U];
__device__ float    g_HD2[(size_t)N2 * U];
__device__ float    g_HD1[(size_t)N1 * U];
// 21 weight chunk images (n-major: word[n*68+k2] = half2(k=2k2,2k2+1) at col n)
__device__ uint32_t g_WT[21 * TILE_WORDS];

#define CH_UP2 0
#define CH_UP3 3
#define CH_UP4 6
#define CH_DN3 9
#define CH_DN2 11
#define CH_DN1 13
#define CH_W2(i) (15 + (i))

// ---------------------------------------------------------------------------
// helpers
// ---------------------------------------------------------------------------
__device__ __forceinline__ float fast_tanh(float x) {
    float e = __expf(2.0f * x);
    return 1.0f - __fdividef(2.0f, e + 1.0f);
}
__device__ __forceinline__ uint32_t h2bits(__half2 h) { return *(uint32_t*)&h; }
__device__ __forceinline__ uint32_t pack2(float x, float y) {
    return h2bits(__floats2half2_rn(x, y));
}
__device__ __forceinline__ void cp_async16(void* dst_smem, const void* src) {
    uint32_t d = (uint32_t)__cvta_generic_to_shared(dst_smem);
    asm volatile("cp.async.cg.shared.global [%0], [%1], 16;" :: "r"(d), "l"(src));
}
#define CP_COMMIT() asm volatile("cp.async.commit_group;" ::: "memory")
#define CP_WAIT_0() asm volatile("cp.async.wait_group 0;" ::: "memory")

__device__ __forceinline__ void prefetch_l2(const void* p) {
    asm volatile("prefetch.global.L2 [%0];" :: "l"(p));
}
__device__ __forceinline__ void red_add_v4(float* p, float4 v) {
    asm volatile("red.global.add.v4.f32 [%0], {%1,%2,%3,%4};"
                 :: "l"(p), "f"(v.x), "f"(v.y), "f"(v.z), "f"(v.w) : "memory");
}
__device__ __forceinline__ void mma_fp16(float c[4],
                                         uint32_t a0, uint32_t a1, uint32_t a2, uint32_t a3,
                                         uint32_t b0, uint32_t b1) {
    asm volatile(
        "mma.sync.aligned.m16n8k16.row.col.f32.f16.f16.f32 "
        "{%0,%1,%2,%3}, {%4,%5,%6,%7}, {%8,%9}, {%0,%1,%2,%3};"
        : "+f"(c[0]), "+f"(c[1]), "+f"(c[2]), "+f"(c[3])
        : "r"(a0), "r"(a1), "r"(a2), "r"(a3), "r"(b0), "r"(b1));
}

// ---------------------------------------------------------------------------
// Weight prep (one launch): 21 chunks -> n-major fp16 tile images.
// ---------------------------------------------------------------------------
struct PrepPtrs { const float* p[21]; };

__global__ void prep_all(PrepPtrs pp, uint32_t* __restrict__ dst)
{
    int e = blockIdx.x * 256 + threadIdx.x;
    if (e >= 21 * TILE_WORDS) return;
    int chunk = e / TILE_WORDS, w = e - chunk * TILE_WORDS;
    int n = w / PW, k2 = w - n * PW;
    uint32_t v = 0;
    if (k2 < 64) {
        const float* W = pp.p[chunk];
        v = pack2(W[(size_t)(2 * k2) * 128 + n], W[(size_t)(2 * k2 + 1) * 128 + n]);
    }
    dst[e] = v;
}

__global__ void zero_all(float4* __restrict__ hd3, float4* __restrict__ hd2,
                         float4* __restrict__ hd1)
{
    const long Z3 = (long)N3 * 32, Z2 = (long)N2 * 32, Z1 = (long)N1 * 32;
    long i = (long)blockIdx.x * 256 + threadIdx.x;
    if (i >= Z3 + Z2 + Z1) return;
    float4 z = make_float4(0.f, 0.f, 0.f, 0.f);
    if (i < Z3)           hd3[i] = z;
    else if (i < Z3 + Z2) hd2[i - Z3] = z;
    else                  hd1[i - Z3 - Z2] = z;
}

// ---------------------------------------------------------------------------
// fp16 fused gather + MLP (+ fused scatter), mma m16n8k16, 2 CTAs/SM:
//   y[r] = tanh( concat(segments(r)) @ W1 + b1 ) @ W2 + b2
// CTA tile 128x128, 256 threads, 8 warps (4m x 2n), warp tile 32x64.
// Round-16 structure (segment rotation + L2 prefetch), plus: scatter epilogue
// assembles 16B quads via lane-pair shuffles and uses red.global.add.v4 —
// HALVES the REDG lane-op count (REDG cost is per lane-op, not per byte).
// ---------------------------------------------------------------------------
template <int NSEG, bool SCATTER, bool SELF16, bool GAT16, bool OUT16>
__global__ __launch_bounds__(NTHR, 2)
void mlp2(const void* __restrict__ selfp,
          const void* __restrict__ gatp,
          const int*  __restrict__ idxg,
          const uint32_t* __restrict__ WB1,   // NSEG chunk images
          const float* __restrict__ b1,
          const uint32_t* __restrict__ WB2,   // 1 chunk image
          const float* __restrict__ b2,
          void* __restrict__ outp,
          const int* __restrict__ idxs)
{
    extern __shared__ uint32_t smu[];
    uint32_t* smA = smu;                // A tile (then H tile)
    uint32_t* smB = smu + TILE_WORDS;   // W tile

    const int t    = threadIdx.x;
    const int lane = t & 31;
    const int cw   = t >> 5;            // warp 0..7
    const int g    = lane >> 2;
    const int tg   = lane & 3;
    const int wm   = (cw & 3) * 32;     // 4 m-warps
    const int wn   = (cw >> 2) * 64;    // 2 n-warps
    const long r0  = (long)blockIdx.x * 128;
    const int arow = t >> 1;            // A-fill: 2 threads per row
    const int ah   = t & 1;             // row half
    const int rot  = (int)(blockIdx.x & 1);   // convoy-breaking rotation

    const uint32_t smemU = (uint32_t)__cvta_generic_to_shared(smu);
    const uint32_t Aaddr = smemU;
    const uint32_t Baddr = smemU + TILE_WORDS * 4;

    // ldmatrix lane offsets (bytes) — layout verified rounds 10-16
    const uint32_t aLane = ((wm + (lane & 15)) * PW + (lane >> 4) * 4) * 4;
    const uint32_t bLane = ((wn + (lane & 7) + ((lane >> 4) << 3)) * PW
                            + ((lane >> 3) & 1) * 4) * 4;

    // gather row indices
    long rows[3];
    rows[0] = r0 + arow;
    if (NSEG == 3) {
        int2 gi = __ldg((const int2*)idxg + (r0 + arow));
        rows[1] = gi.x; rows[2] = gi.y;
    } else {
        rows[1] = r0 + arow;
    }

    float accf[2][8][4];
#pragma unroll
    for (int mt = 0; mt < 2; mt++)
#pragma unroll
        for (int nt = 0; nt < 8; nt++)
#pragma unroll
            for (int c = 0; c < 4; c++) accf[mt][nt][c] = 0.f;

    // ---- fill helpers ----
    auto fillA16 = [&](int seg) {   // fp16 source: pure cp.async
        const uint4* src = (const uint4*)(seg == 0 ? selfp : gatp)
                           + rows[seg] * 16 + ah * 8;
        uint32_t* d = smA + arow * PW + ah * 32;
#pragma unroll
        for (int i = 0; i < 8; i++) cp_async16(d + i * 4, src + i);
    };
    auto fillA32 = [&](int seg) {   // f32 source: LDG -> cvt -> STS
        const float4* src = (const float4*)(seg == 0 ? selfp : gatp)
                            + rows[seg] * 32 + ah * 16;
        uint4* d = (uint4*)(smA + arow * PW + ah * 32);
#pragma unroll
        for (int i = 0; i < 8; i++) {
            float4 v0 = __ldg(src + 2 * i), v1 = __ldg(src + 2 * i + 1);
            uint4 w;
            w.x = pack2(v0.x, v0.y); w.y = pack2(v0.z, v0.w);
            w.z = pack2(v1.x, v1.y); w.w = pack2(v1.z, v1.w);
            d[i] = w;
        }
    };
    auto fillB = [&](const uint32_t* src) {   // weight image: cp.async
        const uint4* s = (const uint4*)src;
#pragma unroll
        for (int i = 0; i < 8; i++)
            cp_async16((uint4*)smB + t + i * 256, s + t + i * 256);
        if (t < 128)
            cp_async16((uint4*)smB + 2048 + t, s + 2048 + t);
    };
    // L2-only prefetch of segment seg's gather rows (this thread's region)
    auto prefetchA = [&](int seg) {
        const bool f16 = (seg == 0) ? SELF16 : GAT16;
        const char* base = (const char*)(seg == 0 ? selfp : gatp);
        if (f16) {
            prefetch_l2(base + rows[seg] * 256 + ah * 128);
        } else {
            const char* p = base + rows[seg] * 512 + ah * 256;
            prefetch_l2(p);
            prefetch_l2(p + 128);
        }
    };

    auto gemm = [&]() {
#pragma unroll
        for (int k = 0; k < 8; k++) {
            uint32_t a[2][4], b[8][2];
#pragma unroll
            for (int mt = 0; mt < 2; mt++)
                asm volatile(
                    "ldmatrix.sync.aligned.m8n8.x4.shared.b16 {%0,%1,%2,%3}, [%4];"
                    : "=r"(a[mt][0]), "=r"(a[mt][1]), "=r"(a[mt][2]), "=r"(a[mt][3])
                    : "r"(Aaddr + aLane + mt * 4352 + k * 32));
#pragma unroll
            for (int nh = 0; nh < 4; nh++)
                asm volatile(
                    "ldmatrix.sync.aligned.m8n8.x4.shared.b16 {%0,%1,%2,%3}, [%4];"
                    : "=r"(b[2*nh][0]), "=r"(b[2*nh][1]),
                      "=r"(b[2*nh+1][0]), "=r"(b[2*nh+1][1])
                    : "r"(Baddr + bLane + nh * 4352 + k * 32));
#pragma unroll
            for (int mt = 0; mt < 2; mt++)
#pragma unroll
                for (int nt = 0; nt < 8; nt++)
                    mma_fp16(accf[mt][nt], a[mt][0], a[mt][1], a[mt][2], a[mt][3],
                             b[nt][0], b[nt][1]);
        }
    };

    // ---- Phase 1: D = X @ W1 over NSEG K-segments (rotated per CTA parity) ----
#pragma unroll
    for (int i = 0; i < NSEG; i++) {
        int seg  = i + rot; if (seg >= NSEG) seg -= NSEG;
        fillB(WB1 + (size_t)seg * TILE_WORDS);
        if (seg == 0) { if (SELF16) fillA16(0);   else fillA32(0);   }
        else          { if (GAT16)  fillA16(seg); else fillA32(seg); }
        CP_COMMIT();
        CP_WAIT_0();
        __syncthreads();            // tiles ready
        if (i + 1 < NSEG) {         // warm L2 for the next segment's gathers
            int nseg = i + 1 + rot; if (nseg >= NSEG) nseg -= NSEG;
            prefetchA(nseg);
        }
        gemm();
        __syncthreads();            // all warps done reading before refill
    }

    // ---- W2 prefetch overlaps H writeback ----
    fillB(WB2);
    CP_COMMIT();
    {
#pragma unroll
        for (int nt = 0; nt < 8; nt++) {
            int col = wn + nt * 8 + 2 * tg;
            float bx = __ldg(&b1[col]), by = __ldg(&b1[col + 1]);
            int wc = col >> 1;
#pragma unroll
            for (int mt = 0; mt < 2; mt++) {
                int row = wm + mt * 16 + g;
                smA[row * PW + wc] =
                    pack2(fast_tanh(accf[mt][nt][0] + bx),
                          fast_tanh(accf[mt][nt][1] + by));
                smA[(row + 8) * PW + wc] =
                    pack2(fast_tanh(accf[mt][nt][2] + bx),
                          fast_tanh(accf[mt][nt][3] + by));
                accf[mt][nt][0] = 0.f; accf[mt][nt][1] = 0.f;
                accf[mt][nt][2] = 0.f; accf[mt][nt][3] = 0.f;
            }
        }
    }
    CP_WAIT_0();
    __syncthreads();

    // ---- Phase 2: Y = H @ W2 ----
    gemm();

    // ---- epilogue: bias2 + (v4 scatter | fp16 store | f32 store) ----
    float bx[8], by[8];
#pragma unroll
    for (int nt = 0; nt < 8; nt++) {
        int col = wn + nt * 8 + 2 * tg;
        bx[nt] = __ldg(&b2[col]);
        by[nt] = __ldg(&b2[col + 1]);
    }
#pragma unroll
    for (int mt = 0; mt < 2; mt++) {
        long ga = r0 + wm + mt * 16 + g;    // rows ga, ga+8
        if (SCATTER) {
            // Lane-pair (tg, tg^1) quad assembly -> red.add.v4 (half the
            // REDG lane-ops of the v2 version; same values, same bytes).
            float* dst = (float*)outp;
            int2 pa = __ldg((const int2*)idxs + ga);        // even lanes use
            int2 pb = __ldg((const int2*)idxs + ga + 8);    // odd lanes use
            const int qcol0 = wn + 4 * (tg >> 1);           // quad base col
#pragma unroll
            for (int nt = 0; nt < 8; nt++) {
                float x0 = accf[mt][nt][0] + bx[nt], y0 = accf[mt][nt][1] + by[nt];
                float x1 = accf[mt][nt][2] + bx[nt], y1 = accf[mt][nt][3] + by[nt];
                float ex0 = __shfl_xor_sync(0xffffffffu, x0, 1);
                float ey0 = __shfl_xor_sync(0xffffffffu, y0, 1);
                float ex1 = __shfl_xor_sync(0xffffffffu, x1, 1);
                float ey1 = __shfl_xor_sync(0xffffffffu, y1, 1);
                int qcol = qcol0 + nt * 8;
                if ((tg & 1) == 0) {
                    float4 v = make_float4(x0, y0, ex0, ey0);   // row ga
                    red_add_v4(dst + (long)pa.x * U + qcol, v);
                    red_add_v4(dst + (long)pa.y * U + qcol, v);
                } else {
                    float4 v = make_float4(ex1, ey1, x1, y1);   // row ga+8
                    red_add_v4(dst + (long)pb.x * U + qcol, v);
                    red_add_v4(dst + (long)pb.y * U + qcol, v);
                }
            }
        } else if (OUT16) {
            uint32_t* dst = (uint32_t*)outp;
#pragma unroll
            for (int nt = 0; nt < 8; nt++) {
                int col = wn + nt * 8 + 2 * tg;
                dst[ga * 64 + (col >> 1)] =
                    pack2(accf[mt][nt][0] + bx[nt], accf[mt][nt][1] + by[nt]);
                dst[(ga + 8) * 64 + (col >> 1)] =
                    pack2(accf[mt][nt][2] + bx[nt], accf[mt][nt][3] + by[nt]);
            }
        } else {
            float* dst = (float*)outp;
#pragma unroll
            for (int nt = 0; nt < 8; nt++) {
                int col = wn + nt * 8 + 2 * tg;
                *(float2*)&dst[ga * U + col] =
                    make_float2(accf[mt][nt][0] + bx[nt], accf[mt][nt][1] + by[nt]);
                *(float2*)&dst[(ga + 8) * U + col] =
                    make_float2(accf[mt][nt][2] + bx[nt], accf[mt][nt][3] + by[nt]);
            }
        }
    }
}

// ---------------------------------------------------------------------------
// Launch sequence: prep(1), zero_all(2), then 6 MLPs
// ---------------------------------------------------------------------------
extern "C" void kernel_launch(void* const* d_in, const int* in_sizes, int n_in,
                              void* d_out, int out_size)
{
    const float* h1 = (const float*)d_in[0];
    const float* h2 = (const float*)d_in[1];
    const float* h3 = (const float*)d_in[2];
    const float* h4 = (const float*)d_in[3];
    const int* idx2 = (const int*)d_in[4];
    const int* idx3 = (const int*)d_in[5];
    const int* idx4 = (const int*)d_in[6];

    const float* up2W1 = (const float*)d_in[7],  *up2b1 = (const float*)d_in[8],
               * up2W2 = (const float*)d_in[9],  *up2b2 = (const float*)d_in[10];
    const float* up3W1 = (const float*)d_in[11], *up3b1 = (const float*)d_in[12],
               * up3W2 = (const float*)d_in[13], *up3b2 = (const float*)d_in[14];
    const float* up4W1 = (const float*)d_in[15], *up4b1 = (const float*)d_in[16],
               * up4W2 = (const float*)d_in[17], *up4b2 = (const float*)d_in[18];
    const float* dn1W1 = (const float*)d_in[19], *dn1b1 = (const float*)d_in[20],
               * dn1W2 = (const float*)d_in[21], *dn1b2 = (const float*)d_in[22];
    const float* dn2W1 = (const float*)d_in[23], *dn2b1 = (const float*)d_in[24],
               * dn2W2 = (const float*)d_in[25], *dn2b2 = (const float*)d_in[26];
    const float* dn3W1 = (const float*)d_in[27], *dn3b1 = (const float*)d_in[28],
               * dn3W2 = (const float*)d_in[29], *dn3b2 = (const float*)d_in[30];

    float* out = (float*)d_out;

    uint32_t *H2h, *H3h, *WT;
    float *HD3, *HD2, *HD1;
    cudaGetSymbolAddress((void**)&H2h, g_H2h);
    cudaGetSymbolAddress((void**)&H3h, g_H3h);
    cudaGetSymbolAddress((void**)&HD3, g_HD3);
    cudaGetSymbolAddress((void**)&HD2, g_HD2);
    cudaGetSymbolAddress((void**)&HD1, g_HD1);
    cudaGetSymbolAddress((void**)&WT,  g_WT);

    const size_t SMEM = (size_t)2 * TILE_WORDS * 4;   // 69632 B -> 2 CTAs/SM
    cudaFuncSetAttribute((const void*)mlp2<3,false,false,false,true >, cudaFuncAttributeMaxDynamicSharedMemorySize, (int)SMEM);
    cudaFuncSetAttribute((const void*)mlp2<3,false,false,true, true >, cudaFuncAttributeMaxDynamicSharedMemorySize, (int)SMEM);
    cudaFuncSetAttribute((const void*)mlp2<3,true, false,true, false>, cudaFuncAttributeMaxDynamicSharedMemorySize, (int)SMEM);
    cudaFuncSetAttribute((const void*)mlp2<2,true, true, false,false>, cudaFuncAttributeMaxDynamicSharedMemorySize, (int)SMEM);
    cudaFuncSetAttribute((const void*)mlp2<2,false,false,false,false>, cudaFuncAttributeMaxDynamicSharedMemorySize, (int)SMEM);

    // ---- single weight-prep launch ----
    {
        PrepPtrs pp;
        const float* w1s[6] = {up2W1, up3W1, up4W1, dn3W1, dn2W1, dn1W1};
        const int   nch[6]  = {3, 3, 3, 2, 2, 2};
        int c = 0;
        for (int s = 0; s < 6; s++)
            for (int j = 0; j < nch[s]; j++) pp.p[c++] = w1s[s] + (size_t)j * 16384;
        const float* w2s[6] = {up2W2, up3W2, up4W2, dn3W2, dn2W2, dn1W2};
        for (int s = 0; s < 6; s++) pp.p[c++] = w2s[s];
        prep_all<<<(21 * TILE_WORDS + 255) / 256, 256>>>(pp, WT);
    }

    // ---- single zero launch (scatter targets) ----
    {
        long tot = (long)(N3 + N2 + N1) * 32;
        zero_all<<<(int)((tot + 255) / 256), 256>>>((float4*)HD3, (float4*)HD2,
                                                    (float4*)HD1);
    }

    const int g1 = N1 / 128, g2 = N2 / 128, g3 = N3 / 128, g4 = N4 / 128;

    // ---- upward pass ----
    mlp2<3,false,false,false,true ><<<g2, NTHR, SMEM>>>(
        h2, h1, idx2, WT + (size_t)CH_UP2 * TILE_WORDS, up2b1,
        WT + (size_t)CH_W2(0) * TILE_WORDS, up2b2, H2h, nullptr);
    mlp2<3,false,false,true ,true ><<<g3, NTHR, SMEM>>>(
        h3, H2h, idx3, WT + (size_t)CH_UP3 * TILE_WORDS, up3b1,
        WT + (size_t)CH_W2(1) * TILE_WORDS, up3b2, H3h, nullptr);
    mlp2<3,true ,false,true ,false><<<g4, NTHR, SMEM>>>(
        h4, H3h, idx4, WT + (size_t)CH_UP4 * TILE_WORDS, up4b1,
        WT + (size_t)CH_W2(2) * TILE_WORDS, up4b2, HD3, idx4);

    // ---- downward pass ----
    mlp2<2,true ,true ,false,false><<<g3, NTHR, SMEM>>>(
        H3h, HD3, nullptr, WT + (size_t)CH_DN3 * TILE_WORDS, dn3b1,
        WT + (size_t)CH_W2(3) * TILE_WORDS, dn3b2, HD2, idx3);
    mlp2<2,true ,true ,false,false><<<g2, NTHR, SMEM>>>(
        H2h, HD2, nullptr, WT + (size_t)CH_DN2 * TILE_WORDS, dn2b1,
        WT + (size_t)CH_W2(4) * TILE_WORDS, dn2b2, HD1, idx2);
    mlp2<2,false,false,false,false><<<g1, NTHR, SMEM>>>(
        h1, HD1, nullptr, WT + (size_t)CH_DN1 * TILE_WORDS, dn1b1,
        WT + (size_t)CH_W2(5) * TILE_WORDS, dn1b2, out, nullptr);
}